// round 6
// baseline (speedup 1.0000x reference)
#include <cuda_runtime.h>

#define NN 100000
#define NE 1000000
#define HD 64
#define NC 16
#define TILE 64
#define PX 68          // padded smem pitch (floats): conflict-free + 16B-aligned rows
#define NTILES ((NN + TILE - 1) / TILE)

// Scratch (allocation-free rule: __device__ globals)
__device__ float g_agg0[(size_t)NN * HD];
__device__ float g_agg1[(size_t)NN * HD];
__device__ float g_cnt0[NN];
__device__ float g_cnt1[NN];

// ---------------------------------------------------------------------------
// Packed f32x2 helpers (ptxas never emits FFMA2 from C++; PTX only)
// ---------------------------------------------------------------------------
typedef unsigned long long u64t;

__device__ __forceinline__ u64t splat2(float x) {
    u64t r;
    asm("mov.b64 %0, {%1, %1};" : "=l"(r) : "f"(x));
    return r;
}
__device__ __forceinline__ void fma2(u64t& d, u64t a, u64t b) {
    asm("fma.rn.f32x2 %0, %1, %2, %0;" : "+l"(d) : "l"(a), "l"(b));
}
__device__ __forceinline__ float2 unpk(u64t v) {
    float2 f;
    asm("mov.b64 {%0, %1}, %2;" : "=f"(f.x), "=f"(f.y) : "l"(v));
    return f;
}

// ---------------------------------------------------------------------------
// Edge phase: 16 threads per edge, one float4 each; red.global.add.v4.f32.
// ---------------------------------------------------------------------------
__global__ void __launch_bounds__(256) edge_kernel(
    const float* __restrict__ feat,
    const int* __restrict__ src,
    const int* __restrict__ dst,
    const int* __restrict__ et)
{
    int e = blockIdx.x * 16 + (threadIdx.x >> 4);
    if (e >= NE) return;
    int l = threadIdx.x & 15;
    int s = __ldg(src + e);
    int d = __ldg(dst + e);
    int t = __ldg(et + e);
    float4 v = *reinterpret_cast<const float4*>(feat + (size_t)s * HD + l * 4);
    float* p = (t ? g_agg0 : g_agg1) + (size_t)d * HD + l * 4;
    asm volatile("red.global.add.v4.f32 [%0], {%1,%2,%3,%4};"
                 :: "l"(p), "f"(v.x), "f"(v.y), "f"(v.z), "f"(v.w)
                 : "memory");
    if (l == 0) atomicAdd((t ? g_cnt0 : g_cnt1) + d, 1.0f);
}

__device__ __forceinline__ float sigmoidf_(float x) {
    return 1.0f / (1.0f + __expf(-x));
}
__device__ __forceinline__ float tanhf_(float x) {
    return 2.0f / (1.0f + __expf(-2.0f * x)) - 1.0f;
}

// ---------------------------------------------------------------------------
// Node phase. 512 threads/block (16 warps -> 4/SMSP), 64-node tiles.
// Thread = (ns = tid&15 : 4 nodes, jh = (tid>>4)&15 : 4 outputs,
//           kh = tid>>8 : k-half [32kh, 32kh+32)).
// kh=1 stages partial accumulators to SC; kh=0 reduces + epilogue.
// ---------------------------------------------------------------------------
__global__ void __launch_bounds__(512, 1) node_kernel(
    const float* __restrict__ feat,
    const float* __restrict__ W0g, const float* __restrict__ b0g,
    const float* __restrict__ W1g, const float* __restrict__ b1g,
    const float* __restrict__ Wihg, const float* __restrict__ Whhg,
    const float* __restrict__ bihg, const float* __restrict__ bhhg,
    const float* __restrict__ Woutg, const float* __restrict__ boutg,
    float* __restrict__ out)
{
    extern __shared__ float sm[];
    float* W0s = sm;                  // [64k][64j]
    float* W1s = W0s + 4096;
    float* WIs = W1s + 4096;          // [64k][192j]
    float* WHs = WIs + 12288;
    float* WOs = WHs + 12288;         // [64k][16c]
    float* B0s = WOs + 1024;
    float* B1s = B0s + 64;
    float* BIs = B1s + 64;
    float* BHs = BIs + 192;
    float* BOs = BHs + 192;
    float* XA  = BOs + 16;            // [64k][PX]
    float* XB  = XA + TILE * PX;
    float* XF  = XB + TILE * PX;
    float* C0s = XF + TILE * PX;
    float* C1s = C0s + 64;
    float* SC  = C1s + 64;            // 8192 floats reduction scratch

    const int tid = threadIdx.x;

    // --- Load weights transposed (k-major). One-time cost per block. ---
    for (int i = tid; i < 4096; i += 512) {
        int j = i & 63, k = i >> 6;
        W0s[k * 64 + j] = W0g[j * 64 + k];
        W1s[k * 64 + j] = W1g[j * 64 + k];
    }
    for (int i = tid; i < 12288; i += 512) {
        int j = i % 192, k = i / 192;
        WIs[k * 192 + j] = Wihg[j * 64 + k];
        WHs[k * 192 + j] = Whhg[j * 64 + k];
    }
    for (int i = tid; i < 1024; i += 512) {
        int c = i & 15, k = i >> 4;
        WOs[k * 16 + c] = Woutg[c * 64 + k];
    }
    if (tid < 64)  { B0s[tid] = b0g[tid]; B1s[tid] = b1g[tid]; }
    if (tid < 192) { BIs[tid] = bihg[tid]; BHs[tid] = bhhg[tid]; }
    if (tid < 16)  { BOs[tid] = boutg[tid]; }

    const int ns = tid & 15;          // node slot: nodes 4*ns .. 4*ns+3
    const int jh = (tid >> 4) & 15;   // output slot: outputs 4*jh .. 4*jh+3 (c=jh in GEMM3)
    const int kh = tid >> 8;          // k-half
    const int kbeg = kh * 32;

    for (int tile = blockIdx.x; tile < NTILES; tile += gridDim.x) {
        __syncthreads();  // weight load (1st iter) / prev-tile buffer reuse
        const int base = tile * TILE;

        // --- Stage agg0/agg1/feat transposed into smem ([k][n], pitch PX). ---
        for (int i = tid; i < TILE * 16; i += 512) {
            int k4 = i >> 6, n = i & 63;
            int gn = base + n;
            float4 a0, a1, f;
            if (gn < NN) {
                a0 = *reinterpret_cast<const float4*>(g_agg0 + (size_t)gn * HD + k4 * 4);
                a1 = *reinterpret_cast<const float4*>(g_agg1 + (size_t)gn * HD + k4 * 4);
                f  = *reinterpret_cast<const float4*>(feat   + (size_t)gn * HD + k4 * 4);
            } else {
                a0 = make_float4(0.f, 0.f, 0.f, 0.f); a1 = a0; f = a0;
            }
            int kb = 4 * k4;
            XA[(kb + 0) * PX + n] = a0.x; XA[(kb + 1) * PX + n] = a0.y;
            XA[(kb + 2) * PX + n] = a0.z; XA[(kb + 3) * PX + n] = a0.w;
            XB[(kb + 0) * PX + n] = a1.x; XB[(kb + 1) * PX + n] = a1.y;
            XB[(kb + 2) * PX + n] = a1.z; XB[(kb + 3) * PX + n] = a1.w;
            XF[(kb + 0) * PX + n] = f.x;  XF[(kb + 1) * PX + n] = f.y;
            XF[(kb + 2) * PX + n] = f.z;  XF[(kb + 3) * PX + n] = f.w;
        }
        if (tid < TILE) {
            int gn = base + tid;
            C0s[tid] = (gn < NN) ? g_cnt0[gn] : 0.0f;
            C1s[tid] = (gn < NN) ? g_cnt1[gn] : 0.0f;
        }
        __syncthreads();

        // ================= GEMM1 (k-split): pre[n][j] =================
        {
            u64t acc2[4][2];
            #pragma unroll
            for (int q = 0; q < 4; q++) { acc2[q][0] = 0ULL; acc2[q][1] = 0ULL; }

            #pragma unroll 8
            for (int kk = 0; kk < 32; kk++) {
                int k = kbeg + kk;
                float4 x0 = *reinterpret_cast<const float4*>(XA + k * PX + 4 * ns);
                float4 x1 = *reinterpret_cast<const float4*>(XB + k * PX + 4 * ns);
                ulonglong2 w0 = *reinterpret_cast<const ulonglong2*>(W0s + k * 64 + 4 * jh);
                ulonglong2 w1 = *reinterpret_cast<const ulonglong2*>(W1s + k * 64 + 4 * jh);
                u64t xs0[4] = {splat2(x0.x), splat2(x0.y), splat2(x0.z), splat2(x0.w)};
                u64t xs1[4] = {splat2(x1.x), splat2(x1.y), splat2(x1.z), splat2(x1.w)};
                #pragma unroll
                for (int q = 0; q < 4; q++) {
                    fma2(acc2[q][0], xs0[q], w0.x);
                    fma2(acc2[q][1], xs0[q], w0.y);
                    fma2(acc2[q][0], xs1[q], w1.x);
                    fma2(acc2[q][1], xs1[q], w1.y);
                }
            }
            float accs[4][4];
            #pragma unroll
            for (int q = 0; q < 4; q++) {
                float2 lo = unpk(acc2[q][0]);
                float2 hi = unpk(acc2[q][1]);
                accs[q][0] = lo.x; accs[q][1] = lo.y;
                accs[q][2] = hi.x; accs[q][3] = hi.y;
            }
            if (kh) {  // stage partials: SC as [64j][64n]
                #pragma unroll
                for (int p = 0; p < 4; p++)
                    *reinterpret_cast<float4*>(SC + (4 * jh + p) * 64 + 4 * ns) =
                        make_float4(accs[0][p], accs[1][p], accs[2][p], accs[3][p]);
            }
            __syncthreads();
            if (!kh) {
                #pragma unroll
                for (int p = 0; p < 4; p++) {
                    float4 v = *reinterpret_cast<const float4*>(SC + (4 * jh + p) * 64 + 4 * ns);
                    accs[0][p] += v.x; accs[1][p] += v.y; accs[2][p] += v.z; accs[3][p] += v.w;
                }
                // bias * counts epilogue
                #pragma unroll
                for (int q = 0; q < 4; q++) {
                    float c0 = C0s[4 * ns + q], c1 = C1s[4 * ns + q];
                    #pragma unroll
                    for (int p = 0; p < 4; p++)
                        accs[q][p] += c0 * B0s[4 * jh + p] + c1 * B1s[4 * jh + p];
                }
                // store Pre^T into XA (aliases dead agg0 tile; all GEMM1 reads of XA done)
                #pragma unroll
                for (int p = 0; p < 4; p++)
                    *reinterpret_cast<float4*>(XA + (4 * jh + p) * PX + 4 * ns) =
                        make_float4(accs[0][p], accs[1][p], accs[2][p], accs[3][p]);
            }
            __syncthreads();
        }

        // ================= GEMM2 (k-split): all 3 gates fused =================
        float fR[4][4], fZ[4][4], fI[4][4], fH[4][4];
        {
            u64t aR2[4][2], aZ2[4][2], aI2[4][2], aH2[4][2];
            #pragma unroll
            for (int q = 0; q < 4; q++) {
                aR2[q][0] = aR2[q][1] = 0ULL;
                aZ2[q][0] = aZ2[q][1] = 0ULL;
                aI2[q][0] = aI2[q][1] = 0ULL;
                aH2[q][0] = aH2[q][1] = 0ULL;
            }
            #pragma unroll 4
            for (int kk = 0; kk < 32; kk++) {
                int k = kbeg + kk;
                float4 pv = *reinterpret_cast<const float4*>(XA + k * PX + 4 * ns);
                float4 fv = *reinterpret_cast<const float4*>(XF + k * PX + 4 * ns);
                ulonglong2 wir = *reinterpret_cast<const ulonglong2*>(WIs + k * 192 +   0 + 4 * jh);
                ulonglong2 whr = *reinterpret_cast<const ulonglong2*>(WHs + k * 192 +   0 + 4 * jh);
                ulonglong2 wiz = *reinterpret_cast<const ulonglong2*>(WIs + k * 192 +  64 + 4 * jh);
                ulonglong2 whz = *reinterpret_cast<const ulonglong2*>(WHs + k * 192 +  64 + 4 * jh);
                ulonglong2 win = *reinterpret_cast<const ulonglong2*>(WIs + k * 192 + 128 + 4 * jh);
                ulonglong2 whn = *reinterpret_cast<const ulonglong2*>(WHs + k * 192 + 128 + 4 * jh);
                u64t ps[4] = {splat2(pv.x), splat2(pv.y), splat2(pv.z), splat2(pv.w)};
                u64t fs[4] = {splat2(fv.x), splat2(fv.y), splat2(fv.z), splat2(fv.w)};
                #pragma unroll
                for (int q = 0; q < 4; q++) {
                    fma2(aR2[q][0], ps[q], wir.x);
                    fma2(aR2[q][1], ps[q], wir.y);
                    fma2(aR2[q][0], fs[q], whr.x);
                    fma2(aR2[q][1], fs[q], whr.y);
                    fma2(aZ2[q][0], ps[q], wiz.x);
                    fma2(aZ2[q][1], ps[q], wiz.y);
                    fma2(aZ2[q][0], fs[q], whz.x);
                    fma2(aZ2[q][1], fs[q], whz.y);
                    fma2(aI2[q][0], ps[q], win.x);
                    fma2(aI2[q][1], ps[q], win.y);
                    fma2(aH2[q][0], fs[q], whn.x);
                    fma2(aH2[q][1], fs[q], whn.y);
                }
            }
            #pragma unroll
            for (int q = 0; q < 4; q++) {
                float2 t;
                t = unpk(aR2[q][0]); fR[q][0] = t.x; fR[q][1] = t.y;
                t = unpk(aR2[q][1]); fR[q][2] = t.x; fR[q][3] = t.y;
                t = unpk(aZ2[q][0]); fZ[q][0] = t.x; fZ[q][1] = t.y;
                t = unpk(aZ2[q][1]); fZ[q][2] = t.x; fZ[q][3] = t.y;
                t = unpk(aI2[q][0]); fI[q][0] = t.x; fI[q][1] = t.y;
                t = unpk(aI2[q][1]); fI[q][2] = t.x; fI[q][3] = t.y;
                t = unpk(aH2[q][0]); fH[q][0] = t.x; fH[q][1] = t.y;
                t = unpk(aH2[q][1]); fH[q][2] = t.x; fH[q][3] = t.y;
            }
        }
        // --- reduction pass 1: R and Z ---
        if (kh) {
            #pragma unroll
            for (int p = 0; p < 4; p++) {
                *reinterpret_cast<float4*>(SC + (4 * jh + p) * 64 + 4 * ns) =
                    make_float4(fR[0][p], fR[1][p], fR[2][p], fR[3][p]);
                *reinterpret_cast<float4*>(SC + (64 + 4 * jh + p) * 64 + 4 * ns) =
                    make_float4(fZ[0][p], fZ[1][p], fZ[2][p], fZ[3][p]);
            }
        }
        __syncthreads();
        if (!kh) {
            #pragma unroll
            for (int p = 0; p < 4; p++) {
                float4 vr = *reinterpret_cast<const float4*>(SC + (4 * jh + p) * 64 + 4 * ns);
                float4 vz = *reinterpret_cast<const float4*>(SC + (64 + 4 * jh + p) * 64 + 4 * ns);
                fR[0][p] += vr.x; fR[1][p] += vr.y; fR[2][p] += vr.z; fR[3][p] += vr.w;
                fZ[0][p] += vz.x; fZ[1][p] += vz.y; fZ[2][p] += vz.z; fZ[3][p] += vz.w;
            }
        }
        __syncthreads();
        // --- reduction pass 2: I and H ---
        if (kh) {
            #pragma unroll
            for (int p = 0; p < 4; p++) {
                *reinterpret_cast<float4*>(SC + (4 * jh + p) * 64 + 4 * ns) =
                    make_float4(fI[0][p], fI[1][p], fI[2][p], fI[3][p]);
                *reinterpret_cast<float4*>(SC + (64 + 4 * jh + p) * 64 + 4 * ns) =
                    make_float4(fH[0][p], fH[1][p], fH[2][p], fH[3][p]);
            }
        }
        __syncthreads();
        if (!kh) {
            #pragma unroll
            for (int p = 0; p < 4; p++) {
                float4 vi = *reinterpret_cast<const float4*>(SC + (4 * jh + p) * 64 + 4 * ns);
                float4 vh = *reinterpret_cast<const float4*>(SC + (64 + 4 * jh + p) * 64 + 4 * ns);
                fI[0][p] += vi.x; fI[1][p] += vi.y; fI[2][p] += vi.z; fI[3][p] += vi.w;
                fH[0][p] += vh.x; fH[1][p] += vh.y; fH[2][p] += vh.z; fH[3][p] += vh.w;
            }
            // --- GRU elementwise epilogue ---
            #pragma unroll
            for (int p = 0; p < 4; p++) {
                int j = 4 * jh + p;
                float br = BIs[j] + BHs[j];
                float bz = BIs[64 + j] + BHs[64 + j];
                float bi = BIs[128 + j];
                float bh = BHs[128 + j];
                float hq[4];
                #pragma unroll
                for (int q = 0; q < 4; q++) {
                    float r  = sigmoidf_(fR[q][p] + br);
                    float z  = sigmoidf_(fZ[q][p] + bz);
                    float nn = tanhf_(fI[q][p] + bi + r * (fH[q][p] + bh));
                    float fv2 = XF[j * PX + 4 * ns + q];
                    hq[q] = (1.0f - z) * nn + z * fv2;
                }
                // store H^T into XB (aliases dead agg1 tile)
                *reinterpret_cast<float4*>(XB + j * PX + 4 * ns) =
                    make_float4(hq[0], hq[1], hq[2], hq[3]);
            }
        }
        __syncthreads();

        // ================= GEMM3 (k-split): out[n][c], c = jh =================
        {
            u64t o2[2] = {0ULL, 0ULL};
            #pragma unroll 8
            for (int kk = 0; kk < 32; kk++) {
                int k = kbeg + kk;
                ulonglong2 h2 = *reinterpret_cast<const ulonglong2*>(XB + k * PX + 4 * ns);
                u64t ws = splat2(WOs[k * 16 + jh]);
                fma2(o2[0], h2.x, ws);
                fma2(o2[1], h2.y, ws);
            }
            float2 olo = unpk(o2[0]);
            float2 ohi = unpk(o2[1]);
            float o[4] = {olo.x, olo.y, ohi.x, ohi.y};
            if (kh) {
                *reinterpret_cast<float4*>(SC + jh * 64 + 4 * ns) =
                    make_float4(o[0], o[1], o[2], o[3]);
            }
            __syncthreads();
            if (!kh) {
                float4 v = *reinterpret_cast<const float4*>(SC + jh * 64 + 4 * ns);
                o[0] += v.x; o[1] += v.y; o[2] += v.z; o[3] += v.w;
                float bo = BOs[jh];
                #pragma unroll
                for (int q = 0; q < 4; q++) {
                    int gn = base + 4 * ns + q;
                    if (gn < NN) out[(size_t)gn * NC + jh] = o[q] + bo;
                }
            }
        }
    }
}

// ---------------------------------------------------------------------------
extern "C" void kernel_launch(void* const* d_in, const int* in_sizes, int n_in,
                              void* d_out, int out_size)
{
    const float* feat = (const float*)d_in[0];
    const int*   src  = (const int*)d_in[1];
    const int*   dst  = (const int*)d_in[2];
    const int*   et   = (const int*)d_in[3];
    const float* W0   = (const float*)d_in[4];
    const float* b0   = (const float*)d_in[5];
    const float* W1   = (const float*)d_in[6];
    const float* b1   = (const float*)d_in[7];
    const float* Wih  = (const float*)d_in[8];
    const float* Whh  = (const float*)d_in[9];
    const float* bih  = (const float*)d_in[10];
    const float* bhh  = (const float*)d_in[11];
    const float* Wout = (const float*)d_in[12];
    const float* bout = (const float*)d_in[13];
    float* out = (float*)d_out;

    void *p0, *p1, *p2, *p3;
    cudaGetSymbolAddress(&p0, g_agg0);
    cudaGetSymbolAddress(&p1, g_agg1);
    cudaGetSymbolAddress(&p2, g_cnt0);
    cudaGetSymbolAddress(&p3, g_cnt1);
    cudaMemsetAsync(p0, 0, sizeof(float) * (size_t)NN * HD);
    cudaMemsetAsync(p1, 0, sizeof(float) * (size_t)NN * HD);
    cudaMemsetAsync(p2, 0, sizeof(float) * NN);
    cudaMemsetAsync(p3, 0, sizeof(float) * NN);

    edge_kernel<<<(NE + 15) / 16, 256>>>(feat, src, dst, et);

    const int SMEM_BYTES = 55696 * 4;  // 222784 B
    cudaFuncSetAttribute(node_kernel,
                         cudaFuncAttributeMaxDynamicSharedMemorySize, SMEM_BYTES);
    node_kernel<<<148, 512, SMEM_BYTES>>>(feat, W0, b0, W1, b1,
                                          Wih, Whh, bih, bhh, Wout, bout, out);
}

// round 7
// speedup vs baseline: 1.0270x; 1.0270x over previous
#include <cuda_runtime.h>

#define NN 100000
#define NE 1000000
#define HD 64
#define NC 16
#define TILE 128
#define PX 128          // smem pitch [k][n]; fixed-k row accesses are conflict-free
#define NTILES ((NN + TILE - 1) / TILE)

// Scratch (allocation-free rule: __device__ globals)
__device__ float g_agg0[(size_t)NN * HD];
__device__ float g_agg1[(size_t)NN * HD];
__device__ float g_cnt0[NN];
__device__ float g_cnt1[NN];

// ---------------------------------------------------------------------------
// Packed f32x2 helpers (ptxas never emits FFMA2 from C++; PTX only)
// ---------------------------------------------------------------------------
typedef unsigned long long u64t;

__device__ __forceinline__ u64t splat2(float x) {
    u64t r;
    asm("mov.b64 %0, {%1, %1};" : "=l"(r) : "f"(x));
    return r;
}
__device__ __forceinline__ void fma2(u64t& d, u64t a, u64t b) {
    asm("fma.rn.f32x2 %0, %1, %2, %0;" : "+l"(d) : "l"(a), "l"(b));
}
__device__ __forceinline__ float2 unpk(u64t v) {
    float2 f;
    asm("mov.b64 {%0, %1}, %2;" : "=f"(f.x), "=f"(f.y) : "l"(v));
    return f;
}

// ---------------------------------------------------------------------------
// Edge phase: 16 threads per edge, one float4 each; red.global.add.v4.f32.
// ---------------------------------------------------------------------------
__global__ void __launch_bounds__(256) edge_kernel(
    const float* __restrict__ feat,
    const int* __restrict__ src,
    const int* __restrict__ dst,
    const int* __restrict__ et)
{
    int e = blockIdx.x * 16 + (threadIdx.x >> 4);
    if (e >= NE) return;
    int l = threadIdx.x & 15;
    int s = __ldg(src + e);
    int d = __ldg(dst + e);
    int t = __ldg(et + e);
    float4 v = *reinterpret_cast<const float4*>(feat + (size_t)s * HD + l * 4);
    float* p = (t ? g_agg0 : g_agg1) + (size_t)d * HD + l * 4;
    asm volatile("red.global.add.v4.f32 [%0], {%1,%2,%3,%4};"
                 :: "l"(p), "f"(v.x), "f"(v.y), "f"(v.z), "f"(v.w)
                 : "memory");
    if (l == 0) atomicAdd((t ? g_cnt0 : g_cnt1) + d, 1.0f);
}

__device__ __forceinline__ float sigmoidf_(float x) {
    return 1.0f / (1.0f + __expf(-x));
}
__device__ __forceinline__ float tanhf_(float x) {
    return 2.0f / (1.0f + __expf(-2.0f * x)) - 1.0f;
}

// ---------------------------------------------------------------------------
// Node phase. 512 threads (16 warps = 4/SMSP), TILE=128 nodes, no k-split.
// Thread: ns = tid&31 -> nodes 4ns..4ns+3 ; js = tid>>5 (warp-uniform!)
//         -> outputs 4js..4js+3 (c = js in GEMM3).
// Warp-uniform js => every weight LDS is a full-warp broadcast (1 wavefront).
// Two smem X buffers (lifecycle): B0: agg0 -> Pre^T -> H^T ; B1: agg1 -> feat^T.
// ---------------------------------------------------------------------------
__global__ void __launch_bounds__(512, 1) node_kernel(
    const float* __restrict__ feat,
    const float* __restrict__ W0g, const float* __restrict__ b0g,
    const float* __restrict__ W1g, const float* __restrict__ b1g,
    const float* __restrict__ Wihg, const float* __restrict__ Whhg,
    const float* __restrict__ bihg, const float* __restrict__ bhhg,
    const float* __restrict__ Woutg, const float* __restrict__ boutg,
    float* __restrict__ out)
{
    extern __shared__ float sm[];
    float* W0s = sm;                  // [64k][64j]
    float* W1s = W0s + 4096;
    float* WIs = W1s + 4096;          // [64k][192j]
    float* WHs = WIs + 12288;
    float* WOs = WHs + 12288;         // [64k][16c]
    float* B0s = WOs + 1024;
    float* B1s = B0s + 64;
    float* BIs = B1s + 64;
    float* BHs = BIs + 192;
    float* BOs = BHs + 192;
    float* B0  = BOs + 16;            // [64][PX]  agg0 -> Pre^T -> H^T
    float* B1  = B0 + 64 * PX;        // [64][PX]  agg1 -> feat^T
    float* C0s = B1 + 64 * PX;        // [128]
    float* C1s = C0s + TILE;          // [128]

    const int tid = threadIdx.x;

    // --- Load weights transposed (k-major). One-time cost per block. ---
    for (int i = tid; i < 4096; i += 512) {
        int j = i & 63, k = i >> 6;
        W0s[k * 64 + j] = W0g[j * 64 + k];
        W1s[k * 64 + j] = W1g[j * 64 + k];
    }
    for (int i = tid; i < 12288; i += 512) {
        int j = i % 192, k = i / 192;
        WIs[k * 192 + j] = Wihg[j * 64 + k];
        WHs[k * 192 + j] = Whhg[j * 64 + k];
    }
    for (int i = tid; i < 1024; i += 512) {
        int c = i & 15, k = i >> 4;
        WOs[k * 16 + c] = Woutg[c * 64 + k];
    }
    if (tid < 64)  { B0s[tid] = b0g[tid]; B1s[tid] = b1g[tid]; }
    if (tid < 192) { BIs[tid] = bihg[tid]; BHs[tid] = bhhg[tid]; }
    if (tid < 16)  { BOs[tid] = boutg[tid]; }

    const int ns = tid & 31;   // node slot: nodes 4*ns .. 4*ns+3
    const int js = tid >> 5;   // output slot (uniform per warp)

    for (int tile = blockIdx.x; tile < NTILES; tile += gridDim.x) {
        __syncthreads();  // weight load (1st iter) / prev-tile buffers free
        const int base = tile * TILE;

        // --- Stage agg0 -> B0, agg1 -> B1, transposed ([k][n]). ---
        for (int i = tid; i < TILE * 16; i += 512) {
            int n = i & 127, k4 = i >> 7;
            int gn = base + n;
            float4 a0, a1;
            if (gn < NN) {
                a0 = *reinterpret_cast<const float4*>(g_agg0 + (size_t)gn * HD + k4 * 4);
                a1 = *reinterpret_cast<const float4*>(g_agg1 + (size_t)gn * HD + k4 * 4);
            } else {
                a0 = make_float4(0.f, 0.f, 0.f, 0.f); a1 = a0;
            }
            int kb = 4 * k4;
            B0[(kb + 0) * PX + n] = a0.x; B0[(kb + 1) * PX + n] = a0.y;
            B0[(kb + 2) * PX + n] = a0.z; B0[(kb + 3) * PX + n] = a0.w;
            B1[(kb + 0) * PX + n] = a1.x; B1[(kb + 1) * PX + n] = a1.y;
            B1[(kb + 2) * PX + n] = a1.z; B1[(kb + 3) * PX + n] = a1.w;
        }
        if (tid < TILE) {
            int gn = base + tid;
            C0s[tid] = (gn < NN) ? g_cnt0[gn] : 0.0f;
            C1s[tid] = (gn < NN) ? g_cnt1[gn] : 0.0f;
        }
        __syncthreads();

        // ================= GEMM1: pre[n][j] =================
        float accs[4][4];
        {
            u64t acc2[4][2];
            #pragma unroll
            for (int q = 0; q < 4; q++) { acc2[q][0] = 0ULL; acc2[q][1] = 0ULL; }

            #pragma unroll 8
            for (int k = 0; k < 64; k++) {
                float4 x0 = *reinterpret_cast<const float4*>(B0 + k * PX + 4 * ns);
                float4 x1 = *reinterpret_cast<const float4*>(B1 + k * PX + 4 * ns);
                ulonglong2 w0 = *reinterpret_cast<const ulonglong2*>(W0s + k * 64 + 4 * js);
                ulonglong2 w1 = *reinterpret_cast<const ulonglong2*>(W1s + k * 64 + 4 * js);
                u64t xs0[4] = {splat2(x0.x), splat2(x0.y), splat2(x0.z), splat2(x0.w)};
                u64t xs1[4] = {splat2(x1.x), splat2(x1.y), splat2(x1.z), splat2(x1.w)};
                #pragma unroll
                for (int q = 0; q < 4; q++) {
                    fma2(acc2[q][0], xs0[q], w0.x);
                    fma2(acc2[q][1], xs0[q], w0.y);
                    fma2(acc2[q][0], xs1[q], w1.x);
                    fma2(acc2[q][1], xs1[q], w1.y);
                }
            }
            #pragma unroll
            for (int q = 0; q < 4; q++) {
                float2 lo = unpk(acc2[q][0]);
                float2 hi = unpk(acc2[q][1]);
                accs[q][0] = lo.x; accs[q][1] = lo.y;
                accs[q][2] = hi.x; accs[q][3] = hi.y;
            }
            // bias * counts epilogue
            #pragma unroll
            for (int q = 0; q < 4; q++) {
                float c0 = C0s[4 * ns + q], c1 = C1s[4 * ns + q];
                #pragma unroll
                for (int p = 0; p < 4; p++)
                    accs[q][p] += c0 * B0s[4 * js + p] + c1 * B1s[4 * js + p];
            }
        }
        __syncthreads();   // all reads of B0(agg0)/B1(agg1) complete

        // write Pre^T into B0 ; stage feat -> B1
        #pragma unroll
        for (int p = 0; p < 4; p++)
            *reinterpret_cast<float4*>(B0 + (4 * js + p) * PX + 4 * ns) =
                make_float4(accs[0][p], accs[1][p], accs[2][p], accs[3][p]);
        for (int i = tid; i < TILE * 16; i += 512) {
            int n = i & 127, k4 = i >> 7;
            int gn = base + n;
            float4 f = (gn < NN)
                ? *reinterpret_cast<const float4*>(feat + (size_t)gn * HD + k4 * 4)
                : make_float4(0.f, 0.f, 0.f, 0.f);
            int kb = 4 * k4;
            B1[(kb + 0) * PX + n] = f.x; B1[(kb + 1) * PX + n] = f.y;
            B1[(kb + 2) * PX + n] = f.z; B1[(kb + 3) * PX + n] = f.w;
        }
        __syncthreads();

        // ================= GEMM2: all 3 gates fused, one k-loop =================
        float fR[4][4], fZ[4][4], fI[4][4], fH[4][4];
        {
            u64t aR2[4][2], aZ2[4][2], aI2[4][2], aH2[4][2];
            #pragma unroll
            for (int q = 0; q < 4; q++) {
                aR2[q][0] = aR2[q][1] = 0ULL;
                aZ2[q][0] = aZ2[q][1] = 0ULL;
                aI2[q][0] = aI2[q][1] = 0ULL;
                aH2[q][0] = aH2[q][1] = 0ULL;
            }
            #pragma unroll 2
            for (int k = 0; k < 64; k++) {
                float4 pv = *reinterpret_cast<const float4*>(B0 + k * PX + 4 * ns);
                float4 fv = *reinterpret_cast<const float4*>(B1 + k * PX + 4 * ns);
                ulonglong2 wir = *reinterpret_cast<const ulonglong2*>(WIs + k * 192 +   0 + 4 * js);
                ulonglong2 whr = *reinterpret_cast<const ulonglong2*>(WHs + k * 192 +   0 + 4 * js);
                ulonglong2 wiz = *reinterpret_cast<const ulonglong2*>(WIs + k * 192 +  64 + 4 * js);
                ulonglong2 whz = *reinterpret_cast<const ulonglong2*>(WHs + k * 192 +  64 + 4 * js);
                ulonglong2 win = *reinterpret_cast<const ulonglong2*>(WIs + k * 192 + 128 + 4 * js);
                ulonglong2 whn = *reinterpret_cast<const ulonglong2*>(WHs + k * 192 + 128 + 4 * js);
                u64t ps[4] = {splat2(pv.x), splat2(pv.y), splat2(pv.z), splat2(pv.w)};
                u64t fs[4] = {splat2(fv.x), splat2(fv.y), splat2(fv.z), splat2(fv.w)};
                #pragma unroll
                for (int q = 0; q < 4; q++) {
                    fma2(aR2[q][0], ps[q], wir.x);
                    fma2(aR2[q][1], ps[q], wir.y);
                    fma2(aR2[q][0], fs[q], whr.x);
                    fma2(aR2[q][1], fs[q], whr.y);
                    fma2(aZ2[q][0], ps[q], wiz.x);
                    fma2(aZ2[q][1], ps[q], wiz.y);
                    fma2(aZ2[q][0], fs[q], whz.x);
                    fma2(aZ2[q][1], fs[q], whz.y);
                    fma2(aI2[q][0], ps[q], win.x);
                    fma2(aI2[q][1], ps[q], win.y);
                    fma2(aH2[q][0], fs[q], whn.x);
                    fma2(aH2[q][1], fs[q], whn.y);
                }
            }
            #pragma unroll
            for (int q = 0; q < 4; q++) {
                float2 t;
                t = unpk(aR2[q][0]); fR[q][0] = t.x; fR[q][1] = t.y;
                t = unpk(aR2[q][1]); fR[q][2] = t.x; fR[q][3] = t.y;
                t = unpk(aZ2[q][0]); fZ[q][0] = t.x; fZ[q][1] = t.y;
                t = unpk(aZ2[q][1]); fZ[q][2] = t.x; fZ[q][3] = t.y;
                t = unpk(aI2[q][0]); fI[q][0] = t.x; fI[q][1] = t.y;
                t = unpk(aI2[q][1]); fI[q][2] = t.x; fI[q][3] = t.y;
                t = unpk(aH2[q][0]); fH[q][0] = t.x; fH[q][1] = t.y;
                t = unpk(aH2[q][1]); fH[q][2] = t.x; fH[q][3] = t.y;
            }
        }
        __syncthreads();   // all reads of B0(Pre) complete -> B0 reusable for H

        // --- GRU elementwise epilogue; write H^T into B0 ---
        #pragma unroll
        for (int p = 0; p < 4; p++) {
            int j = 4 * js + p;
            float br = BIs[j] + BHs[j];
            float bz = BIs[64 + j] + BHs[64 + j];
            float bi = BIs[128 + j];
            float bh = BHs[128 + j];
            float4 fv2 = *reinterpret_cast<const float4*>(B1 + j * PX + 4 * ns);
            const float fvq[4] = {fv2.x, fv2.y, fv2.z, fv2.w};
            float hq[4];
            #pragma unroll
            for (int q = 0; q < 4; q++) {
                float r  = sigmoidf_(fR[q][p] + br);
                float z  = sigmoidf_(fZ[q][p] + bz);
                float nn = tanhf_(fI[q][p] + bi + r * (fH[q][p] + bh));
                hq[q] = (1.0f - z) * nn + z * fvq[q];
            }
            *reinterpret_cast<float4*>(B0 + j * PX + 4 * ns) =
                make_float4(hq[0], hq[1], hq[2], hq[3]);
        }
        __syncthreads();

        // ================= GEMM3: out[n][c], c = js =================
        {
            u64t o2[2] = {0ULL, 0ULL};
            #pragma unroll 8
            for (int k = 0; k < 64; k++) {
                ulonglong2 h2 = *reinterpret_cast<const ulonglong2*>(B0 + k * PX + 4 * ns);
                u64t ws = splat2(WOs[k * 16 + js]);
                fma2(o2[0], h2.x, ws);
                fma2(o2[1], h2.y, ws);
            }
            float2 olo = unpk(o2[0]);
            float2 ohi = unpk(o2[1]);
            float o[4] = {olo.x, olo.y, ohi.x, ohi.y};
            float bo = BOs[js];
            #pragma unroll
            for (int q = 0; q < 4; q++) {
                int gn = base + 4 * ns + q;
                if (gn < NN) out[(size_t)gn * NC + js] = o[q] + bo;
            }
        }
    }
}

// ---------------------------------------------------------------------------
extern "C" void kernel_launch(void* const* d_in, const int* in_sizes, int n_in,
                              void* d_out, int out_size)
{
    const float* feat = (const float*)d_in[0];
    const int*   src  = (const int*)d_in[1];
    const int*   dst  = (const int*)d_in[2];
    const int*   et   = (const int*)d_in[3];
    const float* W0   = (const float*)d_in[4];
    const float* b0   = (const float*)d_in[5];
    const float* W1   = (const float*)d_in[6];
    const float* b1   = (const float*)d_in[7];
    const float* Wih  = (const float*)d_in[8];
    const float* Whh  = (const float*)d_in[9];
    const float* bih  = (const float*)d_in[10];
    const float* bhh  = (const float*)d_in[11];
    const float* Wout = (const float*)d_in[12];
    const float* bout = (const float*)d_in[13];
    float* out = (float*)d_out;

    void *p0, *p1, *p2, *p3;
    cudaGetSymbolAddress(&p0, g_agg0);
    cudaGetSymbolAddress(&p1, g_agg1);
    cudaGetSymbolAddress(&p2, g_cnt0);
    cudaGetSymbolAddress(&p3, g_cnt1);
    cudaMemsetAsync(p0, 0, sizeof(float) * (size_t)NN * HD);
    cudaMemsetAsync(p1, 0, sizeof(float) * (size_t)NN * HD);
    cudaMemsetAsync(p2, 0, sizeof(float) * NN);
    cudaMemsetAsync(p3, 0, sizeof(float) * NN);

    edge_kernel<<<(NE + 15) / 16, 256>>>(feat, src, dst, et);

    // smem: 34320 (weights+biases) + 2*64*128 (B0,B1) + 256 (counts) floats
    const int SMEM_BYTES = (34320 + 2 * 64 * PX + 2 * TILE) * 4;  // 203840 B
    cudaFuncSetAttribute(node_kernel,
                         cudaFuncAttributeMaxDynamicSharedMemorySize, SMEM_BYTES);
    node_kernel<<<148, 512, SMEM_BYTES>>>(feat, W0, b0, W1, b1,
                                          Wih, Whh, bih, bhh, Wout, bout, out);
}